// round 12
// baseline (speedup 1.0000x reference)
#include <cuda_runtime.h>
#include <cstdint>

#define V_TOT  200000
#define KNN    96
#define NSEG   4
#define SEGSZ  50000
#define NBPS   16384
#define NBUCKET (NSEG * NBPS)            // 65536
#define NEDGE  (V_TOT * KNN)
#define INF0   0x7F7F7F7F
#define NB_C   196
#define NB_G   592                       // greedy blocks: 4/SM on 148 SMs, co-resident
#define TPB_G  256

// ---------------- scratch (device globals) ----------------------------------------
__device__ int d_order[V_TOT];
__device__ int d_rank[V_TOT];
__device__ unsigned long long d_tmp[V_TOT];
__device__ int d_hist[NBUCKET];
__device__ int d_cnt[NBUCKET];
__device__ int d_state[V_TOT];           // 0 undecided, 1 centre, 2 dead
__device__ int d_claim[V_TOT];
__device__ int d_amin[V_TOT];
__device__ int d_frontA[V_TOT];
__device__ int d_frontB[V_TOT];
__device__ int d_nf[2];
__device__ int d_pref[V_TOT + 1];
__device__ int d_sel[V_TOT];
__device__ int d_bsum[64];
__device__ int d_csum[256];
__device__ int g_count;                  // grid barrier (zero-init; invariant: 0 at entry/exit)
__device__ volatile int g_sense;

// ---------------- init (sort scratch only; greedy inits its own state) -------------
__global__ void k_init() {
    int i = blockIdx.x * blockDim.x + threadIdx.x;
    int stride = gridDim.x * blockDim.x;
    for (int j = i; j < NBUCKET; j += stride) { d_hist[j] = 0; d_cnt[j] = 0; }
}

// ---------------- sort ------------------------------------------------------------

__device__ __forceinline__ unsigned bucket_of(float u, int seg) {
    unsigned b = (unsigned)(u * 16384.0f);
    if (b > 16383u) b = 16383u;
    return (unsigned)seg * NBPS + (16383u - b);     // segment-major, hier desc
}

__global__ void k_hist(const float* __restrict__ hier) {
    int i = blockIdx.x * blockDim.x + threadIdx.x;
    if (i >= V_TOT) return;
    atomicAdd(&d_hist[bucket_of(hier[i], i / SEGSZ)], 1);
}

__global__ void k_scan1() {
    __shared__ int s[1024];
    int t = threadIdx.x;
    s[t] = d_hist[blockIdx.x * 1024 + t];
    __syncthreads();
    for (int off = 512; off > 0; off >>= 1) {
        if (t < off) s[t] += s[t + off];
        __syncthreads();
    }
    if (t == 0) d_bsum[blockIdx.x] = s[0];
}
__global__ void k_scan3() {
    __shared__ int s[1024];
    __shared__ int s2[64];
    int t = threadIdx.x, b = blockIdx.x;
    if (t < 64) s2[t] = d_bsum[t];
    int x = d_hist[b * 1024 + t];
    s[t] = x;
    __syncthreads();
    for (int off = 1; off < 64; off <<= 1) {
        int v = (t < 64 && t >= off) ? s2[t - off] : 0;
        __syncthreads();
        if (t < 64) s2[t] += v;
        __syncthreads();
    }
    for (int off = 1; off < 1024; off <<= 1) {
        int v = (t >= off) ? s[t - off] : 0;
        __syncthreads();
        s[t] += v;
        __syncthreads();
    }
    int base = (b == 0) ? 0 : s2[b - 1];
    d_hist[b * 1024 + t] = base + s[t] - x;          // exclusive
}

__global__ void k_scatter(const float* __restrict__ hier) {
    int i = blockIdx.x * blockDim.x + threadIdx.x;
    if (i >= V_TOT) return;
    float u = hier[i];
    unsigned inv = 0x3FFFFFFFu - __float_as_uint(u);
    unsigned b = bucket_of(u, i / SEGSZ);
    int pos = d_hist[b] + atomicAdd(&d_cnt[b], 1);
    d_tmp[pos] = ((unsigned long long)inv << 18) | (unsigned)i;
}

__global__ void k_bsort() {
    int b = blockIdx.x * blockDim.x + threadIdx.x;
    if (b >= NBUCKET) return;
    int n = d_cnt[b];
    if (n == 0) return;
    int s = d_hist[b];
    for (int k = 1; k < n; k++) {
        unsigned long long key = d_tmp[s + k];
        int j = k - 1;
        while (j >= 0 && d_tmp[s + j] > key) { d_tmp[s + j + 1] = d_tmp[s + j]; j--; }
        d_tmp[s + j + 1] = key;
    }
    for (int k = 0; k < n; k++) {
        int v = (int)(d_tmp[s + k] & 0x3FFFFull);
        d_order[s + k] = v;
        d_rank[v] = s + k;
    }
}

// ---------------- persistent parallel greedy ---------------------------------------

__device__ __forceinline__ void centre_row(int v, int rv, const int* __restrict__ neighs) {
    const int4* row = (const int4*)(neighs + (size_t)v * KNN);
#pragma unroll
    for (int e = 0; e < KNN / 4; e++) {
        int4 w4 = row[e];
        int w;
        w = w4.x; atomicMin(&d_amin[w], rv); if (d_rank[w] > rv) d_state[w] = 2;
        w = w4.y; atomicMin(&d_amin[w], rv); if (d_rank[w] > rv) d_state[w] = 2;
        w = w4.z; atomicMin(&d_amin[w], rv); if (d_rank[w] > rv) d_state[w] = 2;
        w = w4.w; atomicMin(&d_amin[w], rv); if (d_rank[w] > rv) d_state[w] = 2;
    }
}

// sense-reversing grid barrier. Requires all NB_G blocks resident (4/SM).
// Local sense seeded from g_sense at kernel entry -> clean across graph replays.
__device__ __forceinline__ void gsync(int* s_sense) {
    __syncthreads();
    if (threadIdx.x == 0) {
        int my = *s_sense ^ 1;
        __threadfence();
        if (atomicAdd(&g_count, 1) == NB_G - 1) {
            g_count = 0;
            __threadfence();
            g_sense = my;
        } else {
            while (g_sense != my) { __nanosleep(32); }
        }
        *s_sense = my;
    }
    __syncthreads();
}

__global__ void __launch_bounds__(TPB_G) k_greedy(const int* __restrict__ neighs) {
    __shared__ int s_sense;
    const int gid = blockIdx.x * TPB_G + threadIdx.x;
    const int GS  = NB_G * TPB_G;

    if (threadIdx.x == 0) s_sense = g_sense;
    __syncthreads();

    // phase 0: init
    for (int j = gid; j < V_TOT; j += GS) {
        d_claim[j] = INF0; d_amin[j] = INF0; d_state[j] = 0;
    }
    if (gid < 2) d_nf[gid] = 0;
    gsync(&s_sense);

    // phase 1: claim over all edges (int4; 4 edges share one source rank)
    const int4* n4 = (const int4*)neighs;
    for (int q = gid; q < NEDGE / 4; q += GS) {
        int ru = d_rank[q / (KNN / 4)];
        int4 w = n4[q];
        atomicMin(&d_claim[w.x], ru);
        atomicMin(&d_claim[w.y], ru);
        atomicMin(&d_claim[w.z], ru);
        atomicMin(&d_claim[w.w], ru);
    }
    gsync(&s_sense);

    // phase 2: confirm + build frontier A
    for (int v = gid; v < V_TOT; v += GS) {
        int c = d_claim[v];
        d_claim[v] = INF0;
        int rv = d_rank[v];
        if (c == rv) {
            d_state[v] = 1;
            centre_row(v, rv, neighs);
        } else if (d_state[v] == 0) {
            d_frontA[atomicAdd(&d_nf[0], 1)] = v;
        }
    }
    gsync(&s_sense);

    // phase 3: frontier rounds until convergence (min-rank frontier vertex
    // always confirms -> guaranteed progress)
    int sel = 0;
    while (true) {
        int n = d_nf[sel];                      // stable after gsync
        if (n == 0) break;
        if (gid == 0) d_nf[sel ^ 1] = 0;
        const int* front = sel ? d_frontB : d_frontA;
        int*       fnext = sel ? d_frontA : d_frontB;

        long total = (long)n * KNN;
        for (long idx = gid; idx < total; idx += GS) {
            int u = front[idx / KNN];
            if (d_state[u] != 0) continue;
            atomicMin(&d_claim[neighs[(size_t)u * KNN + (int)(idx % KNN)]], d_rank[u]);
        }
        gsync(&s_sense);

        for (int k = gid; k < n; k += GS) {
            int v = front[k];
            if (d_state[v] != 0) continue;
            int c = d_claim[v];
            d_claim[v] = INF0;
            int rv = d_rank[v];
            if (c == rv) {
                d_state[v] = 1;
                centre_row(v, rv, neighs);
            } else if (d_state[v] == 0) {
                fnext[atomicAdd(&d_nf[sel ^ 1], 1)] = v;
            }
        }
        gsync(&s_sense);
        sel ^= 1;
    }
}

// ---- full-chip scan of centre flags over order positions + sel compaction --------
__device__ __forceinline__ int cflag(int p) {
    return (p < V_TOT && d_state[d_order[p]] == 1) ? 1 : 0;
}
__global__ void k_cscan1() {
    __shared__ int s[1024];
    int t = threadIdx.x;
    s[t] = cflag(blockIdx.x * 1024 + t);
    __syncthreads();
    for (int off = 512; off > 0; off >>= 1) {
        if (t < off) s[t] += s[t + off];
        __syncthreads();
    }
    if (t == 0) d_csum[blockIdx.x] = s[0];
}
__global__ void k_cscan3() {
    __shared__ int s[1024];
    __shared__ int s2[256];
    int t = threadIdx.x, b = blockIdx.x;
    if (t < 256) s2[t] = (t < NB_C) ? d_csum[t] : 0;
    int p = b * 1024 + t;
    int x = cflag(p);
    s[t] = x;
    __syncthreads();
    for (int off = 1; off < 256; off <<= 1) {
        int v = (t < 256 && t >= off) ? s2[t - off] : 0;
        __syncthreads();
        if (t < 256) s2[t] += v;
        __syncthreads();
    }
    for (int off = 1; off < 1024; off <<= 1) {
        int v = (t >= off) ? s[t - off] : 0;
        __syncthreads();
        s[t] += v;
        __syncthreads();
    }
    int base = (b == 0) ? 0 : s2[b - 1];
    int pref = base + s[t] - x;                      // exclusive
    if (p <= V_TOT) d_pref[p] = pref;
    if (x) d_sel[pref] = d_order[p];
}

__global__ void k_final(float* __restrict__ out) {
    int i = blockIdx.x * blockDim.x + threadIdx.x;
    if (i < V_TOT) {
        int total = d_pref[V_TOT];
        out[i] = (i < total) ? (float)d_sel[i] : -1.0f;          // sel
        out[V_TOT + NSEG + 1 + i] = (float)d_pref[d_amin[i]];    // ggather
    }
    if (i < NSEG)  out[V_TOT + i] = (float)d_pref[i * SEGSZ];    // rs
    if (i == NSEG) out[V_TOT + NSEG] = (float)d_pref[V_TOT];
}

// ---------------- launch -----------------------------------------------------------

extern "C" void kernel_launch(void* const* d_in, const int* in_sizes, int n_in,
                              void* d_out, int out_size) {
    const int*   neighs = nullptr;
    const float* hier   = nullptr;
    for (int i = 0; i < n_in; i++) {
        if (in_sizes[i] == NEDGE)       neighs = (const int*)d_in[i];
        else if (in_sizes[i] == V_TOT)  hier   = (const float*)d_in[i];
    }
    float* out = (float*)d_out;

    k_init   <<<256, 256>>>();
    k_hist   <<<(V_TOT + 255) / 256, 256>>>(hier);
    k_scan1  <<<64, 1024>>>();
    k_scan3  <<<64, 1024>>>();
    k_scatter<<<(V_TOT + 255) / 256, 256>>>(hier);
    k_bsort  <<<NBUCKET / 256, 256>>>();

    k_greedy <<<NB_G, TPB_G>>>(neighs);

    k_cscan1 <<<NB_C, 1024>>>();
    k_cscan3 <<<NB_C, 1024>>>();
    k_final  <<<(V_TOT + 255) / 256, 256>>>(out);
}

// round 13
// speedup vs baseline: 1.6287x; 1.6287x over previous
#include <cuda_runtime.h>
#include <cstdint>

#define V_TOT  200000
#define KNN    96
#define NSEG   4
#define SEGSZ  50000
#define NBPS   16384
#define NBUCKET (NSEG * NBPS)            // 65536
#define NEDGE  (V_TOT * KNN)
#define NQUAD  (NEDGE / 4)
#define INF0   0x7F7F7F7F
#define NB_C   196
#define FGRID  2048

// ---------------- scratch (device globals) ----------------------------------------
__device__ int d_order[V_TOT];
__device__ int d_rank[V_TOT];
__device__ unsigned long long d_tmp[V_TOT];
__device__ int d_hist[NBUCKET];
__device__ int d_cnt[NBUCKET];
__device__ int d_state[V_TOT];           // 0 undecided, 1 centre, 2 dead
__device__ int d_claim[V_TOT];
__device__ int d_amin[V_TOT];
__device__ int d_frontA[V_TOT];
__device__ int d_frontB[V_TOT];
__device__ int d_nf[2];
__device__ int d_pref[V_TOT + 1];
__device__ int d_sel[V_TOT];
__device__ int d_bsum[64];
__device__ int d_csum[256];

// ---------------- init: one kernel for all scratch ----------------------------------
__global__ void k_init() {
    int i = blockIdx.x * blockDim.x + threadIdx.x;
    int stride = gridDim.x * blockDim.x;
    for (int j = i; j < NBUCKET; j += stride) { d_hist[j] = 0; d_cnt[j] = 0; }
    for (int j = i; j < V_TOT; j += stride) {
        d_claim[j] = INF0; d_amin[j] = INF0; d_state[j] = 0;
    }
    if (i < 2) d_nf[i] = 0;
}

// ---------------- sort ------------------------------------------------------------

__device__ __forceinline__ unsigned bucket_of(float u, int seg) {
    unsigned b = (unsigned)(u * 16384.0f);
    if (b > 16383u) b = 16383u;
    return (unsigned)seg * NBPS + (16383u - b);     // segment-major, hier desc
}

__global__ void k_hist(const float* __restrict__ hier) {
    int i = blockIdx.x * blockDim.x + threadIdx.x;
    if (i >= V_TOT) return;
    atomicAdd(&d_hist[bucket_of(hier[i], i / SEGSZ)], 1);
}

__global__ void k_scan1() {
    __shared__ int s[1024];
    int t = threadIdx.x;
    s[t] = d_hist[blockIdx.x * 1024 + t];
    __syncthreads();
    for (int off = 512; off > 0; off >>= 1) {
        if (t < off) s[t] += s[t + off];
        __syncthreads();
    }
    if (t == 0) d_bsum[blockIdx.x] = s[0];
}
__global__ void k_scan3() {
    __shared__ int s[1024];
    __shared__ int s2[64];
    int t = threadIdx.x, b = blockIdx.x;
    if (t < 64) s2[t] = d_bsum[t];
    int x = d_hist[b * 1024 + t];
    s[t] = x;
    __syncthreads();
    for (int off = 1; off < 64; off <<= 1) {
        int v = (t < 64 && t >= off) ? s2[t - off] : 0;
        __syncthreads();
        if (t < 64) s2[t] += v;
        __syncthreads();
    }
    for (int off = 1; off < 1024; off <<= 1) {
        int v = (t >= off) ? s[t - off] : 0;
        __syncthreads();
        s[t] += v;
        __syncthreads();
    }
    int base = (b == 0) ? 0 : s2[b - 1];
    d_hist[b * 1024 + t] = base + s[t] - x;          // exclusive
}

__global__ void k_scatter(const float* __restrict__ hier) {
    int i = blockIdx.x * blockDim.x + threadIdx.x;
    if (i >= V_TOT) return;
    float u = hier[i];
    unsigned inv = 0x3FFFFFFFu - __float_as_uint(u);
    unsigned b = bucket_of(u, i / SEGSZ);
    int pos = d_hist[b] + atomicAdd(&d_cnt[b], 1);
    d_tmp[pos] = ((unsigned long long)inv << 18) | (unsigned)i;
}

__global__ void k_bsort() {
    int b = blockIdx.x * blockDim.x + threadIdx.x;
    if (b >= NBUCKET) return;
    int n = d_cnt[b];
    if (n == 0) return;
    int s = d_hist[b];
    for (int k = 1; k < n; k++) {
        unsigned long long key = d_tmp[s + k];
        int j = k - 1;
        while (j >= 0 && d_tmp[s + j] > key) { d_tmp[s + j + 1] = d_tmp[s + j]; j--; }
        d_tmp[s + j + 1] = key;
    }
    for (int k = 0; k < n; k++) {
        int v = (int)(d_tmp[s + k] & 0x3FFFFull);
        d_order[s + k] = v;
        d_rank[v] = s + k;
    }
}

// ---------------- parallel greedy ---------------------------------------------------

__device__ __forceinline__ void centre_row(int v, int rv, const int* __restrict__ neighs) {
    const int4* row = (const int4*)(neighs + (size_t)v * KNN);
#pragma unroll
    for (int e = 0; e < KNN / 4; e++) {
        int4 w4 = row[e];
        int w;
        w = w4.x; atomicMin(&d_amin[w], rv); if (d_rank[w] > rv) d_state[w] = 2;
        w = w4.y; atomicMin(&d_amin[w], rv); if (d_rank[w] > rv) d_state[w] = 2;
        w = w4.z; atomicMin(&d_amin[w], rv); if (d_rank[w] > rv) d_state[w] = 2;
        w = w4.w; atomicMin(&d_amin[w], rv); if (d_rank[w] > rv) d_state[w] = 2;
    }
}

// round 1: all vertices undecided — int4 over edges, 4 edges share one rank load
__global__ void k_claim1(const int* __restrict__ neighs) {
    int q = blockIdx.x * blockDim.x + threadIdx.x;
    if (q >= NQUAD) return;
    int ru = d_rank[q / (KNN / 4)];
    int4 w = ((const int4*)neighs)[q];
    atomicMin(&d_claim[w.x], ru);
    atomicMin(&d_claim[w.y], ru);
    atomicMin(&d_claim[w.z], ru);
    atomicMin(&d_claim[w.w], ru);
}

__global__ void k_confirm1(const int* __restrict__ neighs) {
    int v = blockIdx.x * blockDim.x + threadIdx.x;
    if (v >= V_TOT) return;
    int c = d_claim[v];
    d_claim[v] = INF0;
    int rv = d_rank[v];
    if (c == rv) {
        d_state[v] = 1;
        centre_row(v, rv, neighs);
    } else if (d_state[v] == 0) {
        d_frontA[atomicAdd(&d_nf[0], 1)] = v;
    }
}

// frontier claim: quad-decomposed (n * 24 quads)
__global__ void k_claim_f(const int* __restrict__ neighs,
                          const int* __restrict__ front, int srcSel) {
    if (blockIdx.x == 0 && threadIdx.x == 0) d_nf[srcSel ^ 1] = 0;
    int n = d_nf[srcSel] * (KNN / 4);
    int stride = gridDim.x * blockDim.x;
    for (int idx = blockIdx.x * blockDim.x + threadIdx.x; idx < n; idx += stride) {
        int u = front[idx / (KNN / 4)];
        if (d_state[u] != 0) continue;
        int ru = d_rank[u];
        int4 w = ((const int4*)(neighs + (size_t)u * KNN))[idx % (KNN / 4)];
        atomicMin(&d_claim[w.x], ru);
        atomicMin(&d_claim[w.y], ru);
        atomicMin(&d_claim[w.z], ru);
        atomicMin(&d_claim[w.w], ru);
    }
}

__global__ void k_confirm_f(const int* __restrict__ neighs,
                            const int* __restrict__ front,
                            int* __restrict__ frontNext, int srcSel) {
    int n = d_nf[srcSel];
    int stride = gridDim.x * blockDim.x;
    for (int k = blockIdx.x * blockDim.x + threadIdx.x; k < n; k += stride) {
        int v = front[k];
        if (d_state[v] != 0) continue;
        int c = d_claim[v];
        d_claim[v] = INF0;
        int rv = d_rank[v];
        if (c == rv) {
            d_state[v] = 1;
            centre_row(v, rv, neighs);
        } else if (d_state[v] == 0) {
            frontNext[atomicAdd(&d_nf[srcSel ^ 1], 1)] = v;
        }
    }
}

// per-segment finisher: guaranteed convergence (segments closed under nb()).
__global__ void __launch_bounds__(1024, 1) k_finish(const int* __restrict__ neighs) {
    __shared__ int s_cnt;
    const int seg  = blockIdx.x;
    const int base = seg * SEGSZ;
    const int tid  = threadIdx.x;

    if (tid == 0) s_cnt = 0;
    __syncthreads();
    for (int v = base + tid; v < base + SEGSZ; v += 1024)
        if (d_state[v] == 0) d_frontA[base + atomicAdd(&s_cnt, 1)] = v;
    __syncthreads();
    int cnt = s_cnt;

    int* fa = d_frontA;
    int* fb = d_frontB;
    while (cnt > 0) {
        for (int k = tid; k < cnt; k += 1024) {
            int u  = fa[base + k];
            int ru = d_rank[u];
            const int* row = neighs + (size_t)u * KNN;
#pragma unroll 8
            for (int e = 0; e < KNN; e++) atomicMin(&d_claim[row[e]], ru);
        }
        __syncthreads();
        for (int k = tid; k < cnt; k += 1024) {
            int v = fa[base + k];
            int c = d_claim[v];
            d_claim[v] = INF0;
            int rv = d_rank[v];
            if (c == rv) {
                d_state[v] = 1;
                centre_row(v, rv, neighs);
            }
        }
        __syncthreads();
        if (tid == 0) s_cnt = 0;
        __syncthreads();
        for (int k = tid; k < cnt; k += 1024) {
            int v = fa[base + k];
            if (d_state[v] == 0) fb[base + atomicAdd(&s_cnt, 1)] = v;
        }
        __syncthreads();
        cnt = s_cnt;
        int* t = fa; fa = fb; fb = t;
        __syncthreads();
    }
}

// ---- full-chip scan of centre flags over order positions + sel compaction --------
__device__ __forceinline__ int cflag(int p) {
    return (p < V_TOT && d_state[d_order[p]] == 1) ? 1 : 0;
}
__global__ void k_cscan1() {
    __shared__ int s[1024];
    int t = threadIdx.x;
    s[t] = cflag(blockIdx.x * 1024 + t);
    __syncthreads();
    for (int off = 512; off > 0; off >>= 1) {
        if (t < off) s[t] += s[t + off];
        __syncthreads();
    }
    if (t == 0) d_csum[blockIdx.x] = s[0];
}
__global__ void k_cscan3() {
    __shared__ int s[1024];
    __shared__ int s2[256];
    int t = threadIdx.x, b = blockIdx.x;
    if (t < 256) s2[t] = (t < NB_C) ? d_csum[t] : 0;
    int p = b * 1024 + t;
    int x = cflag(p);
    s[t] = x;
    __syncthreads();
    for (int off = 1; off < 256; off <<= 1) {
        int v = (t < 256 && t >= off) ? s2[t - off] : 0;
        __syncthreads();
        if (t < 256) s2[t] += v;
        __syncthreads();
    }
    for (int off = 1; off < 1024; off <<= 1) {
        int v = (t >= off) ? s[t - off] : 0;
        __syncthreads();
        s[t] += v;
        __syncthreads();
    }
    int base = (b == 0) ? 0 : s2[b - 1];
    int pref = base + s[t] - x;                      // exclusive
    if (p <= V_TOT) d_pref[p] = pref;
    if (x) d_sel[pref] = d_order[p];
}

__global__ void k_final(float* __restrict__ out) {
    int i = blockIdx.x * blockDim.x + threadIdx.x;
    if (i < V_TOT) {
        int total = d_pref[V_TOT];
        out[i] = (i < total) ? (float)d_sel[i] : -1.0f;          // sel
        out[V_TOT + NSEG + 1 + i] = (float)d_pref[d_amin[i]];    // ggather
    }
    if (i < NSEG)  out[V_TOT + i] = (float)d_pref[i * SEGSZ];    // rs
    if (i == NSEG) out[V_TOT + NSEG] = (float)d_pref[V_TOT];
}

// ---------------- launch -----------------------------------------------------------

extern "C" void kernel_launch(void* const* d_in, const int* in_sizes, int n_in,
                              void* d_out, int out_size) {
    const int*   neighs = nullptr;
    const float* hier   = nullptr;
    for (int i = 0; i < n_in; i++) {
        if (in_sizes[i] == NEDGE)       neighs = (const int*)d_in[i];
        else if (in_sizes[i] == V_TOT)  hier   = (const float*)d_in[i];
    }
    float* out = (float*)d_out;

    void *p_fA, *p_fB;
    cudaGetSymbolAddress(&p_fA, d_frontA);
    cudaGetSymbolAddress(&p_fB, d_frontB);
    int* fA = (int*)p_fA;
    int* fB = (int*)p_fB;

    k_init   <<<512, 256>>>();
    k_hist   <<<(V_TOT + 255) / 256, 256>>>(hier);
    k_scan1  <<<64, 1024>>>();
    k_scan3  <<<64, 1024>>>();
    k_scatter<<<(V_TOT + 255) / 256, 256>>>(hier);
    k_bsort  <<<NBUCKET / 256, 256>>>();

    k_claim1  <<<(NQUAD + 255) / 256, 256>>>(neighs);
    k_confirm1<<<(V_TOT + 255) / 256, 256>>>(neighs);

    // 5 frontier rounds: A->B, B->A, A->B, B->A, A->B
    k_claim_f  <<<FGRID, 256>>>(neighs, fA, 0);
    k_confirm_f<<<FGRID, 256>>>(neighs, fA, fB, 0);
    k_claim_f  <<<FGRID, 256>>>(neighs, fB, 1);
    k_confirm_f<<<FGRID, 256>>>(neighs, fB, fA, 1);
    k_claim_f  <<<FGRID, 256>>>(neighs, fA, 0);
    k_confirm_f<<<FGRID, 256>>>(neighs, fA, fB, 0);
    k_claim_f  <<<FGRID, 256>>>(neighs, fB, 1);
    k_confirm_f<<<FGRID, 256>>>(neighs, fB, fA, 1);
    k_claim_f  <<<FGRID, 256>>>(neighs, fA, 0);
    k_confirm_f<<<FGRID, 256>>>(neighs, fA, fB, 0);

    k_finish <<<NSEG, 1024>>>(neighs);

    k_cscan1 <<<NB_C, 1024>>>();
    k_cscan3 <<<NB_C, 1024>>>();
    k_final  <<<(V_TOT + 255) / 256, 256>>>(out);
}

// round 14
// speedup vs baseline: 1.7351x; 1.0654x over previous
#include <cuda_runtime.h>
#include <cstdint>

#define V_TOT  200000
#define KNN    96
#define NSEG   4
#define SEGSZ  50000
#define NBPS   16384
#define NBUCKET (NSEG * NBPS)            // 65536
#define NEDGE  (V_TOT * KNN)
#define NQUAD  (NEDGE / 4)
#define QPV    (KNN / 4)                 // 24 quads per vertex
#define INF0   0x7F7F7F7F
#define NB_C   196
#define FGRID  2048
#define RMASK  0x3FFFFu                  // rank < 2^18
#define DECB   (1u << 24)                // decided (centre or dead)

// ---------------- scratch (device globals) ----------------------------------------
__device__ int d_order[V_TOT];
__device__ unsigned d_rs[V_TOT];         // rank | DECB  (packed)
__device__ unsigned long long d_tmp[V_TOT];
__device__ int d_hist[NBUCKET];
__device__ int d_cnt[NBUCKET];
__device__ int d_state[V_TOT];           // 1 = centre (else 0)
__device__ int d_claim[V_TOT];
__device__ int d_amin[V_TOT];
__device__ int d_frontA[V_TOT];
__device__ int d_frontB[V_TOT];
__device__ int d_nf[2];
__device__ int d_pref[V_TOT + 1];
__device__ int d_sel[V_TOT];
__device__ int d_bsum[64];
__device__ int d_csum[256];

// ---------------- init ---------------------------------------------------------------
__global__ void k_init() {
    int i = blockIdx.x * blockDim.x + threadIdx.x;
    int stride = gridDim.x * blockDim.x;
    for (int j = i; j < NBUCKET; j += stride) { d_hist[j] = 0; d_cnt[j] = 0; }
    for (int j = i; j < V_TOT; j += stride) {
        d_claim[j] = INF0; d_amin[j] = INF0; d_state[j] = 0;
    }
    if (i < 2) d_nf[i] = 0;
}

// ---------------- sort ------------------------------------------------------------

__device__ __forceinline__ unsigned bucket_of(float u, int seg) {
    unsigned b = (unsigned)(u * 16384.0f);
    if (b > 16383u) b = 16383u;
    return (unsigned)seg * NBPS + (16383u - b);
}

__global__ void k_hist(const float* __restrict__ hier) {
    int i = blockIdx.x * blockDim.x + threadIdx.x;
    if (i >= V_TOT) return;
    atomicAdd(&d_hist[bucket_of(hier[i], i / SEGSZ)], 1);
}

__global__ void k_scan1() {
    __shared__ int s[1024];
    int t = threadIdx.x;
    s[t] = d_hist[blockIdx.x * 1024 + t];
    __syncthreads();
    for (int off = 512; off > 0; off >>= 1) {
        if (t < off) s[t] += s[t + off];
        __syncthreads();
    }
    if (t == 0) d_bsum[blockIdx.x] = s[0];
}
__global__ void k_scan3() {
    __shared__ int s[1024];
    __shared__ int s2[64];
    int t = threadIdx.x, b = blockIdx.x;
    if (t < 64) s2[t] = d_bsum[t];
    int x = d_hist[b * 1024 + t];
    s[t] = x;
    __syncthreads();
    for (int off = 1; off < 64; off <<= 1) {
        int v = (t < 64 && t >= off) ? s2[t - off] : 0;
        __syncthreads();
        if (t < 64) s2[t] += v;
        __syncthreads();
    }
    for (int off = 1; off < 1024; off <<= 1) {
        int v = (t >= off) ? s[t - off] : 0;
        __syncthreads();
        s[t] += v;
        __syncthreads();
    }
    int base = (b == 0) ? 0 : s2[b - 1];
    d_hist[b * 1024 + t] = base + s[t] - x;
}

__global__ void k_scatter(const float* __restrict__ hier) {
    int i = blockIdx.x * blockDim.x + threadIdx.x;
    if (i >= V_TOT) return;
    float u = hier[i];
    unsigned inv = 0x3FFFFFFFu - __float_as_uint(u);
    unsigned b = bucket_of(u, i / SEGSZ);
    int pos = d_hist[b] + atomicAdd(&d_cnt[b], 1);
    d_tmp[pos] = ((unsigned long long)inv << 18) | (unsigned)i;
}

__global__ void k_bsort() {
    int b = blockIdx.x * blockDim.x + threadIdx.x;
    if (b >= NBUCKET) return;
    int n = d_cnt[b];
    if (n == 0) return;
    int s = d_hist[b];
    for (int k = 1; k < n; k++) {
        unsigned long long key = d_tmp[s + k];
        int j = k - 1;
        while (j >= 0 && d_tmp[s + j] > key) { d_tmp[s + j + 1] = d_tmp[s + j]; j--; }
        d_tmp[s + j + 1] = key;
    }
    for (int k = 0; k < n; k++) {
        int v = (int)(d_tmp[s + k] & 0x3FFFFull);
        d_order[s + k] = v;
        d_rs[v] = (unsigned)(s + k);
    }
}

// ---------------- parallel greedy ---------------------------------------------------
// Filtered claims: atomicMin only when target undecided AND rank[target] > ru.
// Exact: self-claim removed, so confirm test is claim[v] > rank[v].

__device__ __forceinline__ void claim4(int4 w, unsigned ru) {
    unsigned rs;
    rs = d_rs[w.x]; if (!(rs & DECB) && (rs & RMASK) > ru) atomicMin(&d_claim[w.x], (int)ru);
    rs = d_rs[w.y]; if (!(rs & DECB) && (rs & RMASK) > ru) atomicMin(&d_claim[w.y], (int)ru);
    rs = d_rs[w.z]; if (!(rs & DECB) && (rs & RMASK) > ru) atomicMin(&d_claim[w.z], (int)ru);
    rs = d_rs[w.w]; if (!(rs & DECB) && (rs & RMASK) > ru) atomicMin(&d_claim[w.w], (int)ru);
}

__device__ __forceinline__ void centre_row(int v, unsigned rv, const int* __restrict__ neighs) {
    const int4* row = (const int4*)(neighs + (size_t)v * KNN);
#pragma unroll
    for (int e = 0; e < QPV; e++) {
        int4 w4 = row[e];
        int w; unsigned rs;
        w = w4.x; atomicMin(&d_amin[w], (int)rv); rs = d_rs[w]; if (!(rs & DECB) && (rs & RMASK) > rv) d_rs[w] = rs | DECB;
        w = w4.y; atomicMin(&d_amin[w], (int)rv); rs = d_rs[w]; if (!(rs & DECB) && (rs & RMASK) > rv) d_rs[w] = rs | DECB;
        w = w4.z; atomicMin(&d_amin[w], (int)rv); rs = d_rs[w]; if (!(rs & DECB) && (rs & RMASK) > rv) d_rs[w] = rs | DECB;
        w = w4.w; atomicMin(&d_amin[w], (int)rv); rs = d_rs[w]; if (!(rs & DECB) && (rs & RMASK) > rv) d_rs[w] = rs | DECB;
    }
}

__global__ void k_claim1(const int* __restrict__ neighs) {
    int q = blockIdx.x * blockDim.x + threadIdx.x;
    if (q >= NQUAD) return;
    unsigned ru = d_rs[q / QPV] & RMASK;       // round 1: nobody decided
    claim4(((const int4*)neighs)[q], ru);
}

// warp-aggregated frontier append
__device__ __forceinline__ void wappend(bool want, int v, int* cnt, int* dst) {
    unsigned m = __ballot_sync(0xffffffffu, want);
    if (want) {
        int lane = threadIdx.x & 31;
        int leader = __ffs(m) - 1;
        int pos = 0;
        if (lane == leader) pos = atomicAdd(cnt, __popc(m));
        pos = __shfl_sync(m, pos, leader);
        dst[pos + __popc(m & ((1u << lane) - 1))] = v;
    }
}

__global__ void k_confirm1(const int* __restrict__ neighs) {
    int v = blockIdx.x * blockDim.x + threadIdx.x;
    bool act = v < V_TOT;
    bool surv = false;
    if (act) {
        int c = d_claim[v];
        d_claim[v] = INF0;
        unsigned rv = d_rs[v] & RMASK;
        if (c > (int)rv) {                         // no smaller live claimer -> centre
            d_state[v] = 1;
            d_rs[v] = rv | DECB;
            centre_row(v, rv, neighs);
        } else {
            surv = !(d_rs[v] & DECB);              // may race with dead-mark: benign
        }
    }
    wappend(surv, v, &d_nf[0], d_frontA);
}

__global__ void k_claim_f(const int* __restrict__ neighs,
                          const int* __restrict__ front, int srcSel) {
    if (blockIdx.x == 0 && threadIdx.x == 0) d_nf[srcSel ^ 1] = 0;
    int n = d_nf[srcSel] * QPV;
    int stride = gridDim.x * blockDim.x;
    for (int idx = blockIdx.x * blockDim.x + threadIdx.x; idx < n; idx += stride) {
        int u = front[idx / QPV];
        unsigned urs = d_rs[u];
        if (urs & DECB) continue;
        claim4(((const int4*)(neighs + (size_t)u * KNN))[idx % QPV], urs & RMASK);
    }
}

__global__ void k_confirm_f(const int* __restrict__ neighs,
                            const int* __restrict__ front,
                            int* __restrict__ frontNext, int srcSel) {
    int n = d_nf[srcSel];
    int stride = gridDim.x * blockDim.x;
    for (int k = blockIdx.x * blockDim.x + threadIdx.x; ; k += stride) {
        if (!__ballot_sync(0xffffffffu, k < n)) break;
        bool act = k < n;
        bool surv = false;
        int v = 0;
        if (act) {
            v = front[k];
            unsigned rsv = d_rs[v];
            if (!(rsv & DECB)) {
                int c = d_claim[v];
                d_claim[v] = INF0;
                unsigned rv = rsv & RMASK;
                if (c > (int)rv) {
                    d_state[v] = 1;
                    d_rs[v] = rv | DECB;
                    centre_row(v, rv, neighs);
                } else {
                    surv = !(d_rs[v] & DECB);
                }
            }
        }
        wappend(surv, v, &d_nf[srcSel ^ 1], frontNext);
    }
}

// per-segment finisher: guaranteed convergence (segments closed under nb()).
__global__ void __launch_bounds__(1024, 1) k_finish(const int* __restrict__ neighs) {
    __shared__ int s_cnt;
    const int seg  = blockIdx.x;
    const int base = seg * SEGSZ;
    const int tid  = threadIdx.x;

    if (tid == 0) s_cnt = 0;
    __syncthreads();
    for (int v = base + tid; v < base + SEGSZ; v += 1024)
        if (!(d_rs[v] & DECB)) d_frontA[base + atomicAdd(&s_cnt, 1)] = v;
    __syncthreads();
    int cnt = s_cnt;

    int* fa = d_frontA;
    int* fb = d_frontB;
    while (cnt > 0) {
        for (int k = tid; k < cnt; k += 1024) {
            int u = fa[base + k];
            unsigned urs = d_rs[u];
            if (urs & DECB) continue;
            unsigned ru = urs & RMASK;
            const int4* row = (const int4*)(neighs + (size_t)u * KNN);
#pragma unroll
            for (int e = 0; e < QPV; e++) claim4(row[e], ru);
        }
        __syncthreads();
        for (int k = tid; k < cnt; k += 1024) {
            int v = fa[base + k];
            unsigned rsv = d_rs[v];
            if (rsv & DECB) continue;
            int c = d_claim[v];
            d_claim[v] = INF0;
            unsigned rv = rsv & RMASK;
            if (c > (int)rv) {
                d_state[v] = 1;
                d_rs[v] = rv | DECB;
                centre_row(v, rv, neighs);
            }
        }
        __syncthreads();
        if (tid == 0) s_cnt = 0;
        __syncthreads();
        for (int k = tid; k < cnt; k += 1024) {
            int v = fa[base + k];
            if (!(d_rs[v] & DECB)) fb[base + atomicAdd(&s_cnt, 1)] = v;
        }
        __syncthreads();
        cnt = s_cnt;
        int* t = fa; fa = fb; fb = t;
        __syncthreads();
    }
}

// ---- full-chip scan of centre flags + sel compaction -------------------------------
__device__ __forceinline__ int cflag(int p) {
    return (p < V_TOT && d_state[d_order[p]] == 1) ? 1 : 0;
}
__global__ void k_cscan1() {
    __shared__ int s[1024];
    int t = threadIdx.x;
    s[t] = cflag(blockIdx.x * 1024 + t);
    __syncthreads();
    for (int off = 512; off > 0; off >>= 1) {
        if (t < off) s[t] += s[t + off];
        __syncthreads();
    }
    if (t == 0) d_csum[blockIdx.x] = s[0];
}
__global__ void k_cscan3() {
    __shared__ int s[1024];
    __shared__ int s2[256];
    int t = threadIdx.x, b = blockIdx.x;
    if (t < 256) s2[t] = (t < NB_C) ? d_csum[t] : 0;
    int p = b * 1024 + t;
    int x = cflag(p);
    s[t] = x;
    __syncthreads();
    for (int off = 1; off < 256; off <<= 1) {
        int v = (t < 256 && t >= off) ? s2[t - off] : 0;
        __syncthreads();
        if (t < 256) s2[t] += v;
        __syncthreads();
    }
    for (int off = 1; off < 1024; off <<= 1) {
        int v = (t >= off) ? s[t - off] : 0;
        __syncthreads();
        s[t] += v;
        __syncthreads();
    }
    int base = (b == 0) ? 0 : s2[b - 1];
    int pref = base + s[t] - x;
    if (p <= V_TOT) d_pref[p] = pref;
    if (x) d_sel[pref] = d_order[p];
}

__global__ void k_final(float* __restrict__ out) {
    int i = blockIdx.x * blockDim.x + threadIdx.x;
    if (i < V_TOT) {
        int total = d_pref[V_TOT];
        out[i] = (i < total) ? (float)d_sel[i] : -1.0f;          // sel
        out[V_TOT + NSEG + 1 + i] = (float)d_pref[d_amin[i]];    // ggather
    }
    if (i < NSEG)  out[V_TOT + i] = (float)d_pref[i * SEGSZ];    // rs
    if (i == NSEG) out[V_TOT + NSEG] = (float)d_pref[V_TOT];
}

// ---------------- launch -----------------------------------------------------------

extern "C" void kernel_launch(void* const* d_in, const int* in_sizes, int n_in,
                              void* d_out, int out_size) {
    const int*   neighs = nullptr;
    const float* hier   = nullptr;
    for (int i = 0; i < n_in; i++) {
        if (in_sizes[i] == NEDGE)       neighs = (const int*)d_in[i];
        else if (in_sizes[i] == V_TOT)  hier   = (const float*)d_in[i];
    }
    float* out = (float*)d_out;

    void *p_fA, *p_fB;
    cudaGetSymbolAddress(&p_fA, d_frontA);
    cudaGetSymbolAddress(&p_fB, d_frontB);
    int* fA = (int*)p_fA;
    int* fB = (int*)p_fB;

    k_init   <<<512, 256>>>();
    k_hist   <<<(V_TOT + 255) / 256, 256>>>(hier);
    k_scan1  <<<64, 1024>>>();
    k_scan3  <<<64, 1024>>>();
    k_scatter<<<(V_TOT + 255) / 256, 256>>>(hier);
    k_bsort  <<<NBUCKET / 256, 256>>>();

    k_claim1  <<<(NQUAD + 255) / 256, 256>>>(neighs);
    k_confirm1<<<(V_TOT + 255) / 256, 256>>>(neighs);

    // 5 frontier rounds: A->B, B->A, A->B, B->A, A->B
    k_claim_f  <<<FGRID, 256>>>(neighs, fA, 0);
    k_confirm_f<<<FGRID, 256>>>(neighs, fA, fB, 0);
    k_claim_f  <<<FGRID, 256>>>(neighs, fB, 1);
    k_confirm_f<<<FGRID, 256>>>(neighs, fB, fA, 1);
    k_claim_f  <<<FGRID, 256>>>(neighs, fA, 0);
    k_confirm_f<<<FGRID, 256>>>(neighs, fA, fB, 0);
    k_claim_f  <<<FGRID, 256>>>(neighs, fB, 1);
    k_confirm_f<<<FGRID, 256>>>(neighs, fB, fA, 1);
    k_claim_f  <<<FGRID, 256>>>(neighs, fA, 0);
    k_confirm_f<<<FGRID, 256>>>(neighs, fA, fB, 0);

    k_finish <<<NSEG, 1024>>>(neighs);

    k_cscan1 <<<NB_C, 1024>>>();
    k_cscan3 <<<NB_C, 1024>>>();
    k_final  <<<(V_TOT + 255) / 256, 256>>>(out);
}